// round 9
// baseline (speedup 1.0000x reference)
#include <cuda_runtime.h>
#include <cuda_bf16.h>
#include <mma.h>

// ---------------------------------------------------------------------------
// SparseConvNet on GB300 — round 8: stages 4/5 on WMMA bf16 (mma.sync / HMMA;
// tcgen05 is unavailable because the harness compiles PTX for compute_103,
// not compute_103a). Padded 66^3 row layout: one 128B row per voxel =
// [32ch bf16 hi | 32ch bf16 lo], zeroed guard rows -> each conv tap is a
// contiguous 128-row gather. 3-term bf16 split keeps rel_err ~1e-5.
// ---------------------------------------------------------------------------

#define N0 (128*128*128)
#define N1 (64*64*64)
#define PD   66
#define PD2  (66*66)          // 4356
#define PD3  (66*66*66)       // 287496
#define NTILES 2247           // ceil(PD3/128)
#define GUARD 4480            // > max |tap row offset| = 4423
#define TOTROWS (GUARD + NTILES*128 + GUARD)   // 296576

typedef unsigned long long u64;
typedef unsigned int u32;
typedef __nv_bfloat16 bf16;
using namespace nvcuda;

// fp32 plane buffers for the 128^3 stages
__device__ float4 g_h0a[4u * N0];
__device__ float4 g_h0b[4u * N0];
// padded bf16 hi/lo volumes for level 1 (zero-init covers pads+guards forever)
__device__ uint4 g_p1a[(size_t)TOTROWS * 8];
__device__ uint4 g_p1b[(size_t)TOTROWS * 8];
__device__ uint4 g_p1c[(size_t)TOTROWS * 8];
// weight images for WMMA: [27 taps][32 ci][pitch 40 co] bf16 = 4320 uint4 each
__device__ uint4 g_wh0[4320];
__device__ uint4 g_wl0[4320];
__device__ uint4 g_wh1[4320];
__device__ uint4 g_wl1[4320];
__device__ int   g_list0[N0];
__device__ int   g_m1[N1];
__device__ int   g_cnt[1];

// ---- packed f32x2 helpers --------------------------------------------------
__device__ __forceinline__ u64 pack2(float lo, float hi) {
    u64 d; asm("mov.b64 %0, {%1, %2};" : "=l"(d) : "f"(lo), "f"(hi)); return d;
}
__device__ __forceinline__ void unpack2(u64 v, float& lo, float& hi) {
    asm("mov.b64 {%0, %1}, %2;" : "=f"(lo), "=f"(hi) : "l"(v));
}
__device__ __forceinline__ u64 ffma2(u64 a, u64 b, u64 c) {
    u64 r; asm("fma.rn.f32x2 %0, %1, %2, %3;" : "=l"(r) : "l"(a), "l"(b), "l"(c));
    return r;
}

// ---- bf16 helpers -----------------------------------------------------------
__device__ __forceinline__ u32 bf2(float a, float b) {
    __nv_bfloat162 t = __floats2bfloat162_rn(a, b);
    return *reinterpret_cast<u32*>(&t);
}
__device__ __forceinline__ float bflo(float a) {          // bf16 round-trip
    return __bfloat162float(__float2bfloat16(a));
}

// ---------------------------------------------------------------------------
__global__ void zero_cnt_k() { g_cnt[0] = 0; }

__global__ void build_list0_k(const int* __restrict__ mask) {
    int i = blockIdx.x * blockDim.x + threadIdx.x;
    bool act = mask[i] != 0;
    unsigned b = __ballot_sync(0xffffffffu, act);
    if (!b) return;
    int lane = threadIdx.x & 31;
    int leader = __ffs(b) - 1;
    int pos = 0;
    if (lane == leader) pos = atomicAdd(&g_cnt[0], __popc(b));
    pos = __shfl_sync(0xffffffffu, pos, leader);
    if (act) g_list0[pos + __popc(b & ((1u << lane) - 1u))] = i;
}

__global__ void build_m1_k(const int* __restrict__ mask) {
    int i = blockIdx.x * blockDim.x + threadIdx.x;
    int z = i >> 12, y = (i >> 6) & 63, x = i & 63;
    int act = 0;
    #pragma unroll
    for (int t = 0; t < 27; t++) {
        int zz = 2 * z + t / 9 - 1;
        int yy = 2 * y + (t / 3) % 3 - 1;
        int xx = 2 * x + t % 3 - 1;
        if ((unsigned)zz < 128u && (unsigned)yy < 128u && (unsigned)xx < 128u)
            act |= mask[(zz << 14) | (yy << 7) | xx];
    }
    g_m1[i] = act;
}

// Build WMMA weight images: hi/lo bf16, layout [t][ci][co] with co-pitch 40.
__global__ void pack_w_k(const float* __restrict__ w,
                         uint4* __restrict__ wh, uint4* __restrict__ wl) {
    int e = blockIdx.x * 256 + threadIdx.x;
    if (e >= 27648) return;
    int t = e % 27, ci = (e / 27) % 32, co = e / (27 * 32);
    float v = w[e];
    bf16 h = __float2bfloat16(v);
    float hf = __bfloat162float(h);
    bf16 l = __float2bfloat16(v - hf);
    int idx = t * 1280 + ci * 40 + co;          // elements
    ((unsigned short*)wh)[idx] = *reinterpret_cast<unsigned short*>(&h);
    ((unsigned short*)wl)[idx] = *reinterpret_cast<unsigned short*>(&l);
}

// ---------------------------------------------------------------------------
// Stage 1: conv 3 -> 16 over masked x_feat, 128^3.
__global__ void __launch_bounds__(256) stage1_k(
    const float* __restrict__ xf, const int* __restrict__ mask,
    const float* __restrict__ w, const float* __restrict__ sc,
    const float* __restrict__ sh)
{
    __shared__ u64 sw[27 * 3 * 8];
    int n = g_cnt[0];
    if ((int)(blockIdx.x * 256) >= n) return;
    float* swf = (float*)sw;
    for (int idx = threadIdx.x; idx < 16 * 3 * 27; idx += 256) {
        int co = idx / 81, r = idx % 81, ci = r / 27, t = r % 27;
        swf[((t * 3 + ci) * 8 + (co >> 1)) * 2 + (co & 1)] = w[idx];
    }
    __syncthreads();
    int gid = blockIdx.x * 256 + threadIdx.x;
    if (gid >= n) return;
    int vox = g_list0[gid];
    int z = vox >> 14, y = (vox >> 7) & 127, x = vox & 127;
    u64 acc[8];
    #pragma unroll
    for (int p = 0; p < 8; p++) acc[p] = 0ull;
    for (int t = 0; t < 27; t++) {
        int zz = z + t / 9 - 1, yy = y + (t / 3) % 3 - 1, xx = x + t % 3 - 1;
        if ((unsigned)zz >= 128u || (unsigned)yy >= 128u || (unsigned)xx >= 128u) continue;
        int nb = (zz << 14) | (yy << 7) | xx;
        if (!mask[nb]) continue;
        const u64* wp = &sw[t * 24];
        #pragma unroll
        for (int ci = 0; ci < 3; ci++) {
            float xv = xf[(size_t)ci * N0 + nb];
            u64 xv2 = pack2(xv, xv);
            #pragma unroll
            for (int p = 0; p < 8; p++) acc[p] = ffma2(wp[ci * 8 + p], xv2, acc[p]);
        }
    }
    #pragma unroll
    for (int q = 0; q < 4; q++) {
        float a0, a1, a2, a3;
        unpack2(acc[2 * q],     a0, a1);
        unpack2(acc[2 * q + 1], a2, a3);
        float4 o;
        o.x = fmaxf(fmaf(a0, sc[4 * q + 0], sh[4 * q + 0]), 0.f);
        o.y = fmaxf(fmaf(a1, sc[4 * q + 1], sh[4 * q + 1]), 0.f);
        o.z = fmaxf(fmaf(a2, sc[4 * q + 2], sh[4 * q + 2]), 0.f);
        o.w = fmaxf(fmaf(a3, sc[4 * q + 3], sh[4 * q + 3]), 0.f);
        g_h0a[(size_t)q * N0 + vox] = o;
    }
}

// ---------------------------------------------------------------------------
// Stage 2: 16 -> 16 at 128^3, sparse (list0 + per-neighbor mask check).
__global__ void __launch_bounds__(256) stage2_k(
    const float4* __restrict__ in4, const int* __restrict__ mask,
    const float* __restrict__ w, const float* __restrict__ sc,
    const float* __restrict__ sh, float4* __restrict__ out4)
{
    __shared__ u64 sw[27 * 16 * 8];
    int n = g_cnt[0];
    if ((int)(blockIdx.x * 256) >= n) return;
    float* swf = (float*)sw;
    for (int idx = threadIdx.x; idx < 16 * 16 * 27; idx += 256) {
        int co = idx / (16 * 27), ci = (idx / 27) % 16, t = idx % 27;
        swf[((t * 16 + ci) * 8 + (co >> 1)) * 2 + (co & 1)] = w[idx];
    }
    __syncthreads();
    int gid = blockIdx.x * 256 + threadIdx.x;
    if (gid >= n) return;
    int vox = g_list0[gid];
    int z = vox >> 14, y = (vox >> 7) & 127, x = vox & 127;
    u64 acc[8];
    #pragma unroll
    for (int p = 0; p < 8; p++) acc[p] = 0ull;
    for (int t = 0; t < 27; t++) {
        int zz = z + t / 9 - 1, yy = y + (t / 3) % 3 - 1, xx = x + t % 3 - 1;
        if ((unsigned)zz >= 128u || (unsigned)yy >= 128u || (unsigned)xx >= 128u) continue;
        int nb = (zz << 14) | (yy << 7) | xx;
        if (!mask[nb]) continue;
        float xin[16];
        #pragma unroll
        for (int q = 0; q < 4; q++)
            ((float4*)xin)[q] = in4[(size_t)q * N0 + nb];
        const u64* wp = &sw[t * 16 * 8];
        #pragma unroll
        for (int ci = 0; ci < 16; ci++) {
            u64 xv2 = pack2(xin[ci], xin[ci]);
            #pragma unroll
            for (int p = 0; p < 8; p++) acc[p] = ffma2(wp[ci * 8 + p], xv2, acc[p]);
        }
    }
    #pragma unroll
    for (int q = 0; q < 4; q++) {
        float a0, a1, a2, a3;
        unpack2(acc[2 * q],     a0, a1);
        unpack2(acc[2 * q + 1], a2, a3);
        float4 o;
        o.x = fmaxf(fmaf(a0, sc[4 * q + 0], sh[4 * q + 0]), 0.f);
        o.y = fmaxf(fmaf(a1, sc[4 * q + 1], sh[4 * q + 1]), 0.f);
        o.z = fmaxf(fmaf(a2, sc[4 * q + 2], sh[4 * q + 2]), 0.f);
        o.w = fmaxf(fmaf(a3, sc[4 * q + 3], sh[4 * q + 3]), 0.f);
        out4[(size_t)q * N0 + vox] = o;
    }
}

// ---------------------------------------------------------------------------
// Stage 3: dense stride-2 conv 16 (128^3 fp32 planes) -> 32 (padded bf16 rows).
__global__ void __launch_bounds__(256) down2x4_k(
    const float4* __restrict__ in4, const int* __restrict__ m1,
    const float* __restrict__ w, const float* __restrict__ sc,
    const float* __restrict__ sh, uint4* __restrict__ outP)
{
    extern __shared__ u64 sw[];
    float* swf = (float*)sw;
    for (int idx = threadIdx.x; idx < 32 * 16 * 27; idx += 256) {
        int co = idx / (16 * 27), ci = (idx / 27) % 16, t = idx % 27;
        swf[((t * 16 + ci) * 16 + (co >> 1)) * 2 + (co & 1)] = w[idx];
    }
    __syncthreads();
    int gid  = blockIdx.x * 256 + threadIdx.x;
    int half = gid & 1;
    int vox  = (gid >> 1) * 4;
    int z = vox >> 12, y = (vox >> 6) & 63, x = vox & 63;
    u64 acc[4][8];
    #pragma unroll
    for (int v = 0; v < 4; v++)
        #pragma unroll
        for (int p = 0; p < 8; p++) acc[v][p] = 0ull;
    bool vlo = (x > 0), vhi = (x < 60);
    const float4 z4 = make_float4(0.f, 0.f, 0.f, 0.f);
    #pragma unroll 1
    for (int dzy = 0; dzy < 9; dzy++) {
        int dz = dzy / 3, dy = dzy % 3;
        int zz = 2 * z + dz - 1, yy = 2 * y + dy - 1;
        if ((unsigned)zz >= 128u || (unsigned)yy >= 128u) continue;
        int rb = (zz << 14) | (yy << 7) | (2 * x);
        const u64* wt = &sw[(dzy * 3) * 16 * 16 + half * 8];
        #pragma unroll 1
        for (int q = 0; q < 4; q++) {
            const float4* ip = in4 + (size_t)q * N0 + rb;
            float4 a[10];
            a[0] = vlo ? ip[-1] : z4;
            #pragma unroll
            for (int j = 1; j < 9; j++) a[j] = ip[j - 1];
            a[9] = vhi ? ip[8] : z4;
            const float* af = (const float*)a;
            #pragma unroll
            for (int dx = 0; dx < 3; dx++) {
                const u64* wq = wt + (dx * 16 + q * 4) * 16;
                #pragma unroll
                for (int cl = 0; cl < 4; cl++) {
                    u64 x0 = pack2(af[(0 + dx) * 4 + cl], af[(0 + dx) * 4 + cl]);
                    u64 x1 = pack2(af[(2 + dx) * 4 + cl], af[(2 + dx) * 4 + cl]);
                    u64 x2 = pack2(af[(4 + dx) * 4 + cl], af[(4 + dx) * 4 + cl]);
                    u64 x3 = pack2(af[(6 + dx) * 4 + cl], af[(6 + dx) * 4 + cl]);
                    #pragma unroll
                    for (int p = 0; p < 8; p++) {
                        u64 wv = wq[cl * 16 + p];
                        acc[0][p] = ffma2(wv, x0, acc[0][p]);
                        acc[1][p] = ffma2(wv, x1, acc[1][p]);
                        acc[2][p] = ffma2(wv, x2, acc[2][p]);
                        acc[3][p] = ffma2(wv, x3, acc[3][p]);
                    }
                }
            }
        }
    }
    const float* scb = sc + 16 * half;
    const float* shb = sh + 16 * half;
    #pragma unroll
    for (int v = 0; v < 4; v++) {
        float mk = (float)m1[vox + v];
        u32 hl[8], ll[8];
        #pragma unroll
        for (int qq = 0; qq < 4; qq++) {
            float a0, a1, a2, a3;
            unpack2(acc[v][2 * qq],     a0, a1);
            unpack2(acc[v][2 * qq + 1], a2, a3);
            float o0 = fmaxf(fmaf(a0, scb[4 * qq + 0], shb[4 * qq + 0]), 0.f) * mk;
            float o1 = fmaxf(fmaf(a1, scb[4 * qq + 1], shb[4 * qq + 1]), 0.f) * mk;
            float o2 = fmaxf(fmaf(a2, scb[4 * qq + 2], shb[4 * qq + 2]), 0.f) * mk;
            float o3 = fmaxf(fmaf(a3, scb[4 * qq + 3], shb[4 * qq + 3]), 0.f) * mk;
            hl[2 * qq]     = bf2(o0, o1);
            hl[2 * qq + 1] = bf2(o2, o3);
            ll[2 * qq]     = bf2(o0 - bflo(o0), o1 - bflo(o1));
            ll[2 * qq + 1] = bf2(o2 - bflo(o2), o3 - bflo(o3));
        }
        size_t pr = (size_t)GUARD + (size_t)(z + 1) * PD2 + (y + 1) * PD + (x + v + 1);
        uint4* orow = outP + pr * 8;
        orow[half * 2 + 0]     = *reinterpret_cast<uint4*>(&hl[0]);
        orow[half * 2 + 1]     = *reinterpret_cast<uint4*>(&hl[4]);
        orow[4 + half * 2 + 0] = *reinterpret_cast<uint4*>(&ll[0]);
        orow[4 + half * 2 + 1] = *reinterpret_cast<uint4*>(&ll[4]);
    }
}

// ---------------------------------------------------------------------------
// Stages 4/5: 32 -> 32 conv on the padded volume via WMMA bf16 (HMMA).
// CTA = 128 padded rows. 8 warps: warp w owns rows 16w..16w+15, all 32 co.
// A smem tile: 128 rows x 64 bf16 (hi|lo), pitch 72 elems (bank-spread).
// W smem: [27][32 ci][pitch 40] bf16, hi and lo images.
#define A_PITCH 72
#define A_BUF   (128 * A_PITCH * 2)      // 18432 B per buffer
#define W_PITCH 40
#define W_IMG   (27 * 32 * W_PITCH * 2)  // 69120 B per image
#define SM_WH   (2 * A_BUF)
#define SM_WL   (2 * A_BUF + W_IMG)
#define SM_TOT  (2 * A_BUF + 2 * W_IMG)  // 175104 B

__global__ void __launch_bounds__(256) conv64_wmma_k(
    const uint4* __restrict__ inP,
    const uint4* __restrict__ wh, const uint4* __restrict__ wl,
    const float* __restrict__ sc, const float* __restrict__ sh,
    const int* __restrict__ m1, uint4* __restrict__ outP)
{
    extern __shared__ char smem[];
    const int tid = threadIdx.x, wid = tid >> 5, lid = tid & 31;

    // load weight images (pre-packed, pitch 40)
    {
        uint4* d0 = (uint4*)(smem + SM_WH);
        uint4* d1 = (uint4*)(smem + SM_WL);
        for (int j = tid; j < 4320; j += 256) { d0[j] = wh[j]; d1[j] = wl[j]; }
    }

    const long tilebase = (long)GUARD + (long)blockIdx.x * 128;

    wmma::fragment<wmma::accumulator, 16, 16, 16, float> acc[2];
    wmma::fill_fragment(acc[0], 0.f);
    wmma::fill_fragment(acc[1], 0.f);

    // prefill A buffer 0 with tap 0 (row offset -PD2-PD-1)
    {
        const uint4* src = inP + (size_t)(tilebase - PD2 - PD - 1) * 8;
        uint4* dst = (uint4*)smem;
        for (int idx = tid; idx < 1024; idx += 256) {
            int r = idx >> 3, j = idx & 7;
            dst[r * 9 + j] = src[idx];
        }
    }
    __syncthreads();

    #pragma unroll 1
    for (int t = 0; t < 27; t++) {
        // issue next tap's fill first (LDG latency hides under MMAs)
        if (t + 1 < 27) {
            int tn = t + 1;
            int off = (tn / 9 - 1) * PD2 + ((tn / 3) % 3 - 1) * PD + (tn % 3 - 1);
            const uint4* src = inP + (size_t)(tilebase + off) * 8;
            uint4* dst = (uint4*)(smem + (tn & 1) * A_BUF);
            #pragma unroll
            for (int k = 0; k < 4; k++) {
                int idx = tid + k * 256;
                int r = idx >> 3, j = idx & 7;
                dst[r * 9 + j] = src[idx];
            }
        }
        // compute tap t from buffer t&1
        const bf16* A = (const bf16*)(smem + (t & 1) * A_BUF) + wid * 16 * A_PITCH;
        const bf16* WH = (const bf16*)(smem + SM_WH) + t * 32 * W_PITCH;
        const bf16* WL = (const bf16*)(smem + SM_WL) + t * 32 * W_PITCH;

        wmma::fragment<wmma::matrix_a, 16, 16, 16, bf16, wmma::row_major> ah0, ah1, al0, al1;
        wmma::load_matrix_sync(ah0, A, A_PITCH);
        wmma::load_matrix_sync(ah1, A + 16, A_PITCH);
        wmma::load_matrix_sync(al0, A + 32, A_PITCH);
        wmma::load_matrix_sync(al1, A + 48, A_PITCH);

        #pragma unroll
        for (int nt = 0; nt < 2; nt++) {
            wmma::fragment<wmma::matrix_b, 16, 16, 16, bf16, wmma::row_major> b0, b1;
            wmma::load_matrix_sync(b0, WH + nt * 16, W_PITCH);
            wmma::load_matrix_sync(b1, WH + 16 * W_PITCH + nt * 16, W_PITCH);
            wmma::mma_sync(acc[nt], ah0, b0, acc[nt]);
            wmma::mma_sync(acc[nt], ah1, b1, acc[nt]);
            wmma::mma_sync(acc[nt], al0, b0, acc[nt]);   // A_lo x W_hi
            wmma::mma_sync(acc[nt], al1, b1, acc[nt]);
            wmma::load_matrix_sync(b0, WL + nt * 16, W_PITCH);
            wmma::load_matrix_sync(b1, WL + 16 * W_PITCH + nt * 16, W_PITCH);
            wmma::mma_sync(acc[nt], ah0, b0, acc[nt]);   // A_hi x W_lo
            wmma::mma_sync(acc[nt], ah1, b1, acc[nt]);
        }
        __syncthreads();
    }

    // epilogue: spill accumulators to smem scratch (reuse A buffers)
    float* scr = (float*)smem + wid * 512;               // 16 rows x 32 ch
    wmma::store_matrix_sync(scr,      acc[0], 32, wmma::mem_row_major);
    wmma::store_matrix_sync(scr + 16, acc[1], 32, wmma::mem_row_major);
    __syncwarp();

    int row = lid >> 1, cb = (lid & 1) * 16;
    long v = (long)blockIdx.x * 128 + wid * 16 + row;
    if (v < PD3) {
        int z = (int)(v / PD2);
        int r = (int)(v - (long)z * PD2);
        int y = r / PD, x = r - y * PD;
        float mk = 0.f;
        if (z >= 1 && z <= 64 && y >= 1 && y <= 64 && x >= 1 && x <= 64)
            mk = (float)m1[((z - 1) << 12) | ((y - 1) << 6) | (x - 1)];
        const float* rowp = scr + row * 32 + cb;
        u32 hl[8], ll[8];
        #pragma unroll
        for (int c = 0; c < 8; c++) {
            float o0 = fmaxf(fmaf(rowp[2 * c],     sc[cb + 2 * c],     sh[cb + 2 * c]),     0.f) * mk;
            float o1 = fmaxf(fmaf(rowp[2 * c + 1], sc[cb + 2 * c + 1], sh[cb + 2 * c + 1]), 0.f) * mk;
            hl[c] = bf2(o0, o1);
            ll[c] = bf2(o0 - bflo(o0), o1 - bflo(o1));
        }
        uint4* orow = outP + (size_t)(GUARD + v) * 8;
        int b = cb >> 3;                                  // 0 or 2
        orow[b]     = *reinterpret_cast<uint4*>(&hl[0]);
        orow[b + 1] = *reinterpret_cast<uint4*>(&hl[4]);
        orow[4 + b]     = *reinterpret_cast<uint4*>(&ll[0]);
        orow[4 + b + 1] = *reinterpret_cast<uint4*>(&ll[4]);
    }
}

// ---------------------------------------------------------------------------
// Trilinear sampling of the final padded bf16 volume at 65536 coords.
__global__ void __launch_bounds__(256) sample_k(
    const float* __restrict__ coords, const uint4* __restrict__ volP,
    float* __restrict__ out)
{
    int p = blockIdx.x * 256 + threadIdx.x;
    if (p >= 65536) return;
    float fx = (coords[3 * p + 0] + 1.f) * 0.5f * 63.f;
    float fy = (coords[3 * p + 1] + 1.f) * 0.5f * 63.f;
    float fz = (coords[3 * p + 2] + 1.f) * 0.5f * 63.f;
    float x0f = floorf(fx), y0f = floorf(fy), z0f = floorf(fz);
    float tx = fx - x0f, ty = fy - y0f, tz = fz - z0f;
    int x0 = (int)x0f, y0 = (int)y0f, z0 = (int)z0f;
    float acc[32];
    #pragma unroll
    for (int c = 0; c < 32; c++) acc[c] = 0.f;
    #pragma unroll
    for (int dz = 0; dz < 2; dz++)
    #pragma unroll
    for (int dy = 0; dy < 2; dy++)
    #pragma unroll
    for (int dx = 0; dx < 2; dx++) {
        int xi = x0 + dx, yi = y0 + dy, zi = z0 + dz;
        if (xi < 0 || xi >= 64 || yi < 0 || yi >= 64 || zi < 0 || zi >= 64) continue;
        float wgt = (dx ? tx : 1.f - tx) * (dy ? ty : 1.f - ty) * (dz ? tz : 1.f - tz);
        size_t pr = (size_t)GUARD + (size_t)(zi + 1) * PD2 + (yi + 1) * PD + (xi + 1);
        const uint4* rp = volP + pr * 8;
        #pragma unroll
        for (int q = 0; q < 4; q++) {
            uint4 H = rp[q], L = rp[4 + q];
            const u32* hw = (const u32*)&H;
            const u32* lw = (const u32*)&L;
            #pragma unroll
            for (int j = 0; j < 4; j++) {
                float2 hf = __bfloat1622float2(*reinterpret_cast<const __nv_bfloat162*>(&hw[j]));
                float2 lf = __bfloat1622float2(*reinterpret_cast<const __nv_bfloat162*>(&lw[j]));
                int c = q * 8 + j * 2;
                acc[c]     += (hf.x + lf.x) * wgt;
                acc[c + 1] += (hf.y + lf.y) * wgt;
            }
        }
    }
    float4* op = (float4*)(out + (size_t)p * 32);
    #pragma unroll
    for (int q = 0; q < 8; q++)
        op[q] = make_float4(acc[4 * q], acc[4 * q + 1], acc[4 * q + 2], acc[4 * q + 3]);
}

// ---------------------------------------------------------------------------
extern "C" void kernel_launch(void* const* d_in, const int* in_sizes, int n_in,
                              void* d_out, int out_size)
{
    const float* x_feat = (const float*)d_in[0];
    const int*   mask   = (const int*)d_in[1];
    const float* coords = (const float*)d_in[2];
    const float* w0a = (const float*)d_in[3];
    const float* s0a = (const float*)d_in[4];
    const float* b0a = (const float*)d_in[5];
    const float* w0b = (const float*)d_in[6];
    const float* s0b = (const float*)d_in[7];
    const float* b0b = (const float*)d_in[8];
    const float* wd0 = (const float*)d_in[9];
    const float* sd0 = (const float*)d_in[10];
    const float* bd0 = (const float*)d_in[11];
    const float* w1a = (const float*)d_in[12];
    const float* s1a = (const float*)d_in[13];
    const float* b1a = (const float*)d_in[14];
    const float* w1b = (const float*)d_in[15];
    const float* s1b = (const float*)d_in[16];
    const float* b1b = (const float*)d_in[17];
    float* out = (float*)d_out;

    float4 *h0a, *h0b;
    uint4 *p1a, *p1b, *p1c, *wh0, *wl0, *wh1, *wl1;
    int *m1p;
    cudaGetSymbolAddress((void**)&h0a, g_h0a);
    cudaGetSymbolAddress((void**)&h0b, g_h0b);
    cudaGetSymbolAddress((void**)&p1a, g_p1a);
    cudaGetSymbolAddress((void**)&p1b, g_p1b);
    cudaGetSymbolAddress((void**)&p1c, g_p1c);
    cudaGetSymbolAddress((void**)&wh0, g_wh0);
    cudaGetSymbolAddress((void**)&wl0, g_wl0);
    cudaGetSymbolAddress((void**)&wh1, g_wh1);
    cudaGetSymbolAddress((void**)&wl1, g_wl1);
    cudaGetSymbolAddress((void**)&m1p, g_m1);

    cudaFuncSetAttribute(down2x4_k,
                         cudaFuncAttributeMaxDynamicSharedMemorySize, 27 * 16 * 16 * 8);
    cudaFuncSetAttribute(conv64_wmma_k,
                         cudaFuncAttributeMaxDynamicSharedMemorySize, SM_TOT);

    zero_cnt_k<<<1, 1>>>();
    build_list0_k<<<N0 / 256, 256>>>(mask);
    build_m1_k<<<N1 / 256, 256>>>(mask);
    pack_w_k<<<108, 256>>>(w1a, wh0, wl0);
    pack_w_k<<<108, 256>>>(w1b, wh1, wl1);
    stage1_k<<<N0 / 256, 256>>>(x_feat, mask, w0a, s0a, b0a);
    stage2_k<<<N0 / 256, 256>>>(h0a, mask, w0b, s0b, b0b, h0b);
    down2x4_k<<<512, 256, 27 * 16 * 16 * 8>>>(h0b, m1p, wd0, sd0, bd0, p1a);
    conv64_wmma_k<<<NTILES, 256, SM_TOT>>>(p1a, wh0, wl0, s1a, b1a, m1p, p1b);
    conv64_wmma_k<<<NTILES, 256, SM_TOT>>>(p1b, wh1, wl1, s1b, b1b, m1p, p1c);
    sample_k<<<65536 / 256, 256>>>(coords, p1c, out);
}